// round 14
// baseline (speedup 1.0000x reference)
#include <cuda_runtime.h>
#include <cuda_fp16.h>
#include <cstdint>

#define B_   2
#define S_   2048
#define D_   1024
#define H_   16
#define HD_  64
#define MTOT (B_ * S_)   // 4096
#define DD   (D_ * D_)

// ---------------------------------------------------------------------------
// Device scratch (static — no cudaMalloc allowed). Single fp16 everywhere.
// ---------------------------------------------------------------------------
__device__ __half g_x[MTOT * D_];
__device__ __half g_q[MTOT * D_];
__device__ __half g_k[MTOT * D_];
__device__ __half g_v[MTOT * D_];
__device__ __half g_a[MTOT * D_];        // attn out (mis-reshaped layout)
__device__ __half g_wT[4 * DD];          // W^T [n][k], q/k/v/o

// ---------------------------------------------------------------------------
// PTX helpers (sm_80+ only: cp.async, ldmatrix, mma.sync)
// ---------------------------------------------------------------------------
__device__ __forceinline__ uint32_t smem_u32(const void* p) {
    uint32_t a;
    asm("{ .reg .u64 t; cvta.to.shared.u64 t, %1; cvt.u32.u64 %0, t; }"
        : "=r"(a) : "l"(p));
    return a;
}
__device__ __forceinline__ void cp16(uint32_t d, const void* s) {
    asm volatile("cp.async.cg.shared.global [%0], [%1], 16;" :: "r"(d), "l"(s));
}
#define CP_COMMIT() asm volatile("cp.async.commit_group;")
#define CP_WAIT1()  asm volatile("cp.async.wait_group 1;")
#define CP_WAIT0()  asm volatile("cp.async.wait_group 0;")

__device__ __forceinline__ void ldm4(uint32_t* r, uint32_t a) {
    asm volatile("ldmatrix.sync.aligned.m8n8.x4.shared.b16 {%0,%1,%2,%3}, [%4];"
                 : "=r"(r[0]), "=r"(r[1]), "=r"(r[2]), "=r"(r[3]) : "r"(a));
}
__device__ __forceinline__ void ldm4t(uint32_t* r, uint32_t a) {
    asm volatile("ldmatrix.sync.aligned.m8n8.x4.trans.shared.b16 {%0,%1,%2,%3}, [%4];"
                 : "=r"(r[0]), "=r"(r[1]), "=r"(r[2]), "=r"(r[3]) : "r"(a));
}
__device__ __forceinline__ void hmma(float* c, const uint32_t* a, const uint32_t* b) {
    asm volatile(
        "mma.sync.aligned.m16n8k16.row.col.f32.f16.f16.f32 "
        "{%0,%1,%2,%3}, {%4,%5,%6,%7}, {%8,%9}, {%0,%1,%2,%3};"
        : "+f"(c[0]), "+f"(c[1]), "+f"(c[2]), "+f"(c[3])
        : "r"(a[0]), "r"(a[1]), "r"(a[2]), "r"(a[3]), "r"(b[0]), "r"(b[1]));
}
__device__ __forceinline__ float ex2(float x) {
    float r; asm("ex2.approx.ftz.f32 %0, %1;" : "=f"(r) : "f"(x)); return r;
}
__device__ __forceinline__ float qmax(float v) {
    v = fmaxf(v, __shfl_xor_sync(0xFFFFFFFFu, v, 1));
    v = fmaxf(v, __shfl_xor_sync(0xFFFFFFFFu, v, 2));
    return v;
}
__device__ __forceinline__ float qsum(float v) {
    v += __shfl_xor_sync(0xFFFFFFFFu, v, 1);
    v += __shfl_xor_sync(0xFFFFFFFFu, v, 2);
    return v;
}
__device__ __forceinline__ uint32_t packh(float a, float b) {
    __half2 t = __floats2half2_rn(a, b);
    return *(uint32_t*)&t;
}

// ---------------------------------------------------------------------------
// Conversion kernels
// ---------------------------------------------------------------------------
__global__ void __launch_bounds__(256)
conv_x_kernel(const float* __restrict__ in)
{
    int i = blockIdx.x * 256 + threadIdx.x;
    float4 v = ((const float4*)in)[i];
    ((__half2*)g_x)[2 * i]     = __floats2half2_rn(v.x, v.y);
    ((__half2*)g_x)[2 * i + 1] = __floats2half2_rn(v.z, v.w);
}

__global__ void __launch_bounds__(256)
conv_wT_kernel(const float* __restrict__ Wq, const float* __restrict__ Wk,
               const float* __restrict__ Wv, const float* __restrict__ Wo)
{
    const float* W = (blockIdx.z == 0) ? Wq : (blockIdx.z == 1) ? Wk
                    : (blockIdx.z == 2) ? Wv : Wo;
    __half* T = g_wT + (size_t)blockIdx.z * DD;

    __shared__ float tile[32][33];
    const int tx = threadIdx.x & 31, ty = threadIdx.x >> 5;
    const int n0 = blockIdx.x * 32, k0 = blockIdx.y * 32;
#pragma unroll
    for (int i = 0; i < 4; i++)
        tile[ty + 8 * i][tx] = W[(size_t)(k0 + ty + 8 * i) * D_ + n0 + tx];
    __syncthreads();
#pragma unroll
    for (int i = 0; i < 4; i++)
        T[(size_t)(n0 + ty + 8 * i) * D_ + k0 + tx] = __float2half(tile[tx][ty + 8 * i]);
}

// ---------------------------------------------------------------------------
// HMMA fp16 GEMM: C = A @ B^T (B stored [n][k]).  (unchanged from R13 — WIN)
// CTA 128x128, 8 warps (2m x 4n), K-chunk 64, 3-stage cp.async ring.
// mode: 0 -> fp32 C + bias; 1 -> fp16 C.
// ---------------------------------------------------------------------------
#define KCH   64
#define NCH   (D_ / KCH)        // 16
#define LDKB  144               // 64 fp16 (128B) + 16B pad
#define T_A    0
#define T_B    18432
#define STAGE  36864
#define GSMEM  (3 * STAGE)      // 110592

__device__ __forceinline__ void hmma_gemm_body(
    const __half* __restrict__ A, const __half* __restrict__ B,
    float* __restrict__ C, const float* __restrict__ bias,
    __half* __restrict__ Ch, int mode)
{
    extern __shared__ char sm[];
    const uint32_t sb = smem_u32(sm);
    const int tid  = threadIdx.x;
    const int lane = tid & 31;
    const int wid  = tid >> 5;
    const int wm   = (wid & 1) * 64;
    const int wn   = (wid >> 1) * 32;
    const int m0   = blockIdx.y * 128;
    const int n0   = blockIdx.x * 128;

    const uint32_t aoff = (uint32_t)((wm + (lane & 15)) * LDKB + (lane >> 4) * 16);
    const uint32_t boff = (uint32_t)((wn + (lane & 7) + ((lane >> 4) & 1) * 8) * LDKB
                                     + ((lane >> 3) & 1) * 16);

    float acc[4][4][4];
#pragma unroll
    for (int i = 0; i < 4; i++)
#pragma unroll
        for (int j = 0; j < 4; j++)
#pragma unroll
            for (int q = 0; q < 4; q++) acc[i][j][q] = 0.f;

    auto issue = [&](int c, int s) {
        const int k0 = c * KCH;
        const uint32_t st = sb + s * STAGE;
#pragma unroll
        for (int t = 0; t < 4; t++) {
            int idx = tid + t * 256;
            int row = idx >> 3, q = idx & 7;
            uint32_t so = (uint32_t)(row * LDKB + q * 16);
            cp16(st + T_A + so, A + (size_t)(m0 + row) * D_ + k0 + q * 8);
            cp16(st + T_B + so, B + (size_t)(n0 + row) * D_ + k0 + q * 8);
        }
        CP_COMMIT();
    };

    issue(0, 0);
    issue(1, 1);
    for (int c = 0; c < NCH; ++c) {
        if (c + 1 < NCH) CP_WAIT1(); else CP_WAIT0();
        __syncthreads();
        if (c + 2 < NCH) issue(c + 2, (c + 2) % 3);

        const uint32_t st = sb + (c % 3) * STAGE;
        const uint32_t a_b = st + T_A + aoff;
        const uint32_t b_b = st + T_B + boff;

#pragma unroll
        for (int ks = 0; ks < 4; ks++) {
            const uint32_t ko = ks * 32;
            uint32_t ah[4][4], bf[2][4];
#pragma unroll
            for (int i = 0; i < 4; i++)
                ldm4(ah[i], a_b + ko + i * (16 * LDKB));
#pragma unroll
            for (int jp = 0; jp < 2; jp++)
                ldm4(bf[jp], b_b + ko + jp * (16 * LDKB));
#pragma unroll
            for (int i = 0; i < 4; i++)
#pragma unroll
                for (int jp = 0; jp < 2; jp++) {
                    hmma(acc[i][2 * jp],     ah[i], bf[jp]);
                    hmma(acc[i][2 * jp + 1], ah[i], bf[jp] + 2);
                }
        }
    }

    const int gid = lane >> 2, tig = lane & 3;
#pragma unroll
    for (int i = 0; i < 4; i++) {
        const int row = m0 + wm + i * 16 + gid;
#pragma unroll
        for (int j = 0; j < 4; j++) {
            const int col = n0 + wn + j * 8 + tig * 2;
            size_t o0 = (size_t)row * D_ + col;
            size_t o1 = (size_t)(row + 8) * D_ + col;
            if (mode == 1) {
                *(__half2*)(Ch + o0) = __floats2half2_rn(acc[i][j][0], acc[i][j][1]);
                *(__half2*)(Ch + o1) = __floats2half2_rn(acc[i][j][2], acc[i][j][3]);
            } else {
                float b0 = bias[col], b1 = bias[col + 1];
                *(float2*)(C + o0) = make_float2(acc[i][j][0] + b0, acc[i][j][1] + b1);
                *(float2*)(C + o1) = make_float2(acc[i][j][2] + b0, acc[i][j][3] + b1);
            }
        }
    }
}

__global__ void __launch_bounds__(256, 2)
hmma_qkv_kernel()
{
    const int z = blockIdx.z;
    __half* Ch = (z == 0) ? g_q : (z == 1) ? g_k : g_v;
    hmma_gemm_body(g_x, g_wT + (size_t)z * DD, nullptr, nullptr, Ch, 1);
}

__global__ void __launch_bounds__(256, 2)
hmma_out_kernel(const float* __restrict__ bo, float* __restrict__ out)
{
    hmma_gemm_body(g_a, g_wT + 3ull * DD, out, bo, nullptr, 0);
}

// ---------------------------------------------------------------------------
// HMMA flash attention, single fp16. R12 loop structure (2-stage, measured
// best) + deferred-l reduction + warp-uniform causal block skips.
// CTA = (qb, h, b); 8 warps x 16 q rows; K/V fragments via ldmatrix.x4.
// ---------------------------------------------------------------------------
#define FQ    0
#define FST   18432          // stages base (Q tile = 128*144)
#define FSTG  18432          // per-stage: K at 0 (9216), V at 9216
#define FSMEM (FST + 2 * FSTG)   // 55296
#define QSC   0.1803368801f  // 0.125 * log2(e)

template<bool MASKED>
__device__ __forceinline__ void ftile(
    uint32_t st, int kv0, int q0w, int row0, int row1, int lane,
    const uint32_t (&qh)[4][4],
    float& m0, float& m1, float& l0, float& l1, float (&O)[8][4])
{
    const int tig = lane & 3;
    const int rmax = q0w + 15;             // warp-uniform max query row
    float s[8][4];
#pragma unroll
    for (int j = 0; j < 8; j++)
#pragma unroll
        for (int c = 0; c < 4; c++) s[j][c] = 0.f;

    // ---- S = Q @ K^T  (K x4: j and j+1 per load; skip fully-masked pairs)
    const uint32_t kb0 = st + (uint32_t)(((lane & 7) + ((lane >> 4) & 1) * 8) * 144
                                         + ((lane >> 3) & 1) * 16);
#pragma unroll
    for (int kk = 0; kk < 4; kk++) {
        const uint32_t kb = kb0 + kk * 32;
#pragma unroll
        for (int j = 0; j < 8; j += 2) {
            if (MASKED && kv0 + j * 8 > rmax) continue;   // warp-uniform skip
            uint32_t kf[4];
            ldm4(kf, kb + j * (8 * 144));
            hmma(s[j],     qh[kk], kf);
            hmma(s[j + 1], qh[kk], kf + 2);
        }
    }

    // ---- scale + mask + row max
    float mx0 = -1e30f, mx1 = -1e30f;
#pragma unroll
    for (int j = 0; j < 8; j++) {
        if (MASKED && kv0 + j * 8 > rmax) { s[j][0] = s[j][1] = s[j][2] = s[j][3] = -1e30f; continue; }
#pragma unroll
        for (int c = 0; c < 4; c++) {
            float v = s[j][c] * QSC;
            if (MASKED) {
                int col = kv0 + j * 8 + tig * 2 + (c & 1);
                int row = (c < 2) ? row0 : row1;
                if (col > row) v = -1e30f;
            }
            s[j][c] = v;
            if (c < 2) mx0 = fmaxf(mx0, v); else mx1 = fmaxf(mx1, v);
        }
    }
    mx0 = qmax(mx0); mx1 = qmax(mx1);
    const float m0n = fmaxf(m0, mx0), m1n = fmaxf(m1, mx1);
    const float a0 = ex2(m0 - m0n), a1 = ex2(m1 - m1n);
    m0 = m0n; m1 = m1n;

    float ts0 = 0.f, ts1 = 0.f;
    uint32_t pH[2][8];
#pragma unroll
    for (int j = 0; j < 8; j++) {
        if (MASKED && kv0 + j * 8 > rmax) { pH[0][j] = 0u; pH[1][j] = 0u; continue; }
        float p00 = ex2(s[j][0] - m0n), p01 = ex2(s[j][1] - m0n);
        float p10 = ex2(s[j][2] - m1n), p11 = ex2(s[j][3] - m1n);
        if (MASKED) {   // guard fully-masked lanes
            if (s[j][0] < -1e29f) p00 = 0.f;
            if (s[j][1] < -1e29f) p01 = 0.f;
            if (s[j][2] < -1e29f) p10 = 0.f;
            if (s[j][3] < -1e29f) p11 = 0.f;
        }
        ts0 += p00 + p01; ts1 += p10 + p11;
        pH[0][j] = packh(p00, p01);
        pH[1][j] = packh(p10, p11);
    }
    // deferred l: keep per-thread partial sums (reduced once in epilogue)
    l0 = l0 * a0 + ts0;
    l1 = l1 * a1 + ts1;
#pragma unroll
    for (int j = 0; j < 8; j++) {
        O[j][0] *= a0; O[j][1] *= a0; O[j][2] *= a1; O[j][3] *= a1;
    }

    // ---- O += P @ V  (V x4 trans; skip fully-masked kv row blocks)
    const uint32_t vb0 = st + 9216
        + (uint32_t)(((lane & 7) + ((lane >> 3) & 1) * 8) * 144
                     + ((lane >> 4) & 1) * 16);
#pragma unroll
    for (int kk = 0; kk < 4; kk++) {
        if (MASKED && kv0 + kk * 16 > rmax) continue;      // warp-uniform skip
        uint32_t ah[4] = { pH[0][2 * kk], pH[1][2 * kk],
                           pH[0][2 * kk + 1], pH[1][2 * kk + 1] };
        const uint32_t vb = vb0 + kk * (16 * 144);
#pragma unroll
        for (int j = 0; j < 8; j += 2) {
            uint32_t vf[4];
            ldm4t(vf, vb + j * 16);
            hmma(O[j],     ah, vf);
            hmma(O[j + 1], ah, vf + 2);
        }
    }
}

__global__ void __launch_bounds__(256, 2)
flash_hmma_kernel()
{
    extern __shared__ char fsm[];
    const uint32_t sb = smem_u32(fsm);
    const int tid = threadIdx.x, lane = tid & 31, wid = tid >> 5;
    const int qb = gridDim.x - 1 - blockIdx.x;   // big tiles first
    const int h = blockIdx.y, b = blockIdx.z;
    const int ntiles = qb * 2 + 2;

    auto issueT = [&](int t, int s) {
        const uint32_t st = sb + FST + s * FSTG;
        const int kv0 = t * 64;
#pragma unroll
        for (int i = 0; i < 2; i++) {
            int c = tid + i * 256;
            int row = c >> 3, q = c & 7;
            size_t g = (size_t)(b * S_ + kv0 + row) * D_ + h * HD_ + q * 8;
            uint32_t so = (uint32_t)(row * 144 + q * 16);
            cp16(st + so,        g_k + g);
            cp16(st + 9216 + so, g_v + g);
        }
        CP_COMMIT();
    };

    // Q + tile0 (group 0), tile1 (group 1)
    {
#pragma unroll
        for (int i = 0; i < 4; i++) {
            int c = tid + i * 256;
            int row = c >> 3, q = c & 7;
            size_t g = (size_t)(b * S_ + qb * 128 + row) * D_ + h * HD_ + q * 8;
            cp16(sb + FQ + (uint32_t)(row * 144 + q * 16), g_q + g);
        }
        const uint32_t st = sb + FST;
#pragma unroll
        for (int i = 0; i < 2; i++) {
            int c = tid + i * 256;
            int row = c >> 3, q = c & 7;
            size_t g = (size_t)(b * S_ + row) * D_ + h * HD_ + q * 8;
            uint32_t so = (uint32_t)(row * 144 + q * 16);
            cp16(st + so,        g_k + g);
            cp16(st + 9216 + so, g_v + g);
        }
        CP_COMMIT();
        issueT(1, 1);
    }

    const int gid = lane >> 2;
    const int q0w = qb * 128 + wid * 16;
    const int row0 = q0w + gid, row1 = row0 + 8;
    float m0 = -1e30f, m1 = -1e30f, l0 = 0.f, l1 = 0.f;
    float O[8][4];
#pragma unroll
    for (int j = 0; j < 8; j++)
#pragma unroll
        for (int c = 0; c < 4; c++) O[j][c] = 0.f;
    uint32_t qh[4][4];
    bool qloaded = false;

    for (int t = 0; t < ntiles; t++) {
        if (t + 1 < ntiles) CP_WAIT1(); else CP_WAIT0();
        __syncthreads();
        if (!qloaded) {
            const uint32_t qa = (uint32_t)((wid * 16 + (lane & 15)) * 144
                                           + (lane >> 4) * 16);
#pragma unroll
            for (int kk = 0; kk < 4; kk++)
                ldm4(qh[kk], sb + FQ + qa + kk * 32);
            qloaded = true;
        }
        const uint32_t st = sb + FST + (t & 1) * FSTG;
        const int kv0 = t * 64;
        if (q0w + 15 >= kv0) {
            if (kv0 + 63 > q0w)
                ftile<true >(st, kv0, q0w, row0, row1, lane, qh, m0, m1, l0, l1, O);
            else
                ftile<false>(st, kv0, q0w, row0, row1, lane, qh, m0, m1, l0, l1, O);
        }
        __syncthreads();
        if (t + 2 < ntiles) issueT(t + 2, t & 1);
    }

    // epilogue: reduce l across the quad once, normalize, write fp16 layout
    l0 = qsum(l0); l1 = qsum(l1);
    const float inv0 = 1.f / l0, inv1 = 1.f / l1;
    const int tig = lane & 3;
#pragma unroll
    for (int j = 0; j < 8; j++) {
        const int d = j * 8 + tig * 2;
        size_t o0 = (size_t)(b * S_ + h * 128 + (row0 >> 4)) * D_ + (row0 & 15) * 64 + d;
        size_t o1 = (size_t)(b * S_ + h * 128 + (row1 >> 4)) * D_ + (row1 & 15) * 64 + d;
        *(__half2*)(g_a + o0) = __floats2half2_rn(O[j][0] * inv0, O[j][1] * inv0);
        *(__half2*)(g_a + o1) = __floats2half2_rn(O[j][2] * inv1, O[j][3] * inv1);
    }
}

// ---------------------------------------------------------------------------
// Launch
// ---------------------------------------------------------------------------
extern "C" void kernel_launch(void* const* d_in, const int* in_sizes, int n_in,
                              void* d_out, int out_size)
{
    const float* x  = (const float*)d_in[0];
    const float* Wq = (const float*)d_in[1];
    const float* Wk = (const float*)d_in[2];
    const float* Wv = (const float*)d_in[3];
    const float* Wo = (const float*)d_in[4];
    const float* bo = (const float*)d_in[5];
    float* out = (float*)d_out;

    cudaFuncSetAttribute(hmma_qkv_kernel,
                         cudaFuncAttributeMaxDynamicSharedMemorySize, GSMEM);
    cudaFuncSetAttribute(hmma_out_kernel,
                         cudaFuncAttributeMaxDynamicSharedMemorySize, GSMEM);
    cudaFuncSetAttribute(flash_hmma_kernel,
                         cudaFuncAttributeMaxDynamicSharedMemorySize, FSMEM);

    const int n4 = MTOT * D_ / 4;

    conv_x_kernel<<<n4 / 256, 256>>>(x);
    conv_wT_kernel<<<dim3(32, 32, 4), 256>>>(Wq, Wk, Wv, Wo);

    hmma_qkv_kernel<<<dim3(D_ / 128, MTOT / 128, 3), 256, GSMEM>>>();

    flash_hmma_kernel<<<dim3(S_ / 128, H_, B_), 256, FSMEM>>>();

    hmma_out_kernel<<<dim3(D_ / 128, MTOT / 128, 1), 256, GSMEM>>>(bo, out);
}

// round 15
// speedup vs baseline: 1.0175x; 1.0175x over previous
#include <cuda_runtime.h>
#include <cuda_fp16.h>
#include <cstdint>

#define B_   2
#define S_   2048
#define D_   1024
#define H_   16
#define HD_  64
#define MTOT (B_ * S_)   // 4096
#define DD   (D_ * D_)

// ---------------------------------------------------------------------------
// Device scratch (static — no cudaMalloc allowed). Single fp16 everywhere.
// ---------------------------------------------------------------------------
__device__ __half g_x[MTOT * D_];
__device__ __half g_q[MTOT * D_];
__device__ __half g_k[MTOT * D_];
__device__ __half g_v[MTOT * D_];
__device__ __half g_a[MTOT * D_];        // attn out (mis-reshaped layout)
__device__ __half g_wT[4 * DD];          // W^T [n][k], q/k/v/o

// ---------------------------------------------------------------------------
// PTX helpers (sm_80+ only: cp.async, ldmatrix, mma.sync)
// ---------------------------------------------------------------------------
__device__ __forceinline__ uint32_t smem_u32(const void* p) {
    uint32_t a;
    asm("{ .reg .u64 t; cvta.to.shared.u64 t, %1; cvt.u32.u64 %0, t; }"
        : "=r"(a) : "l"(p));
    return a;
}
__device__ __forceinline__ void cp16(uint32_t d, const void* s) {
    asm volatile("cp.async.cg.shared.global [%0], [%1], 16;" :: "r"(d), "l"(s));
}
#define CP_COMMIT() asm volatile("cp.async.commit_group;")
#define CP_WAIT1()  asm volatile("cp.async.wait_group 1;")
#define CP_WAIT0()  asm volatile("cp.async.wait_group 0;")

__device__ __forceinline__ void ldm4(uint32_t* r, uint32_t a) {
    asm volatile("ldmatrix.sync.aligned.m8n8.x4.shared.b16 {%0,%1,%2,%3}, [%4];"
                 : "=r"(r[0]), "=r"(r[1]), "=r"(r[2]), "=r"(r[3]) : "r"(a));
}
__device__ __forceinline__ void ldm4t(uint32_t* r, uint32_t a) {
    asm volatile("ldmatrix.sync.aligned.m8n8.x4.trans.shared.b16 {%0,%1,%2,%3}, [%4];"
                 : "=r"(r[0]), "=r"(r[1]), "=r"(r[2]), "=r"(r[3]) : "r"(a));
}
__device__ __forceinline__ void hmma(float* c, const uint32_t* a, const uint32_t* b) {
    asm volatile(
        "mma.sync.aligned.m16n8k16.row.col.f32.f16.f16.f32 "
        "{%0,%1,%2,%3}, {%4,%5,%6,%7}, {%8,%9}, {%0,%1,%2,%3};"
        : "+f"(c[0]), "+f"(c[1]), "+f"(c[2]), "+f"(c[3])
        : "r"(a[0]), "r"(a[1]), "r"(a[2]), "r"(a[3]), "r"(b[0]), "r"(b[1]));
}
__device__ __forceinline__ float ex2(float x) {
    float r; asm("ex2.approx.ftz.f32 %0, %1;" : "=f"(r) : "f"(x)); return r;
}
__device__ __forceinline__ float qmax(float v) {
    v = fmaxf(v, __shfl_xor_sync(0xFFFFFFFFu, v, 1));
    v = fmaxf(v, __shfl_xor_sync(0xFFFFFFFFu, v, 2));
    return v;
}
__device__ __forceinline__ float qsum(float v) {
    v += __shfl_xor_sync(0xFFFFFFFFu, v, 1);
    v += __shfl_xor_sync(0xFFFFFFFFu, v, 2);
    return v;
}
__device__ __forceinline__ uint32_t packh(float a, float b) {
    __half2 t = __floats2half2_rn(a, b);
    return *(uint32_t*)&t;
}

// ---------------------------------------------------------------------------
// Conversion kernels
// ---------------------------------------------------------------------------
__global__ void __launch_bounds__(256)
conv_x_kernel(const float* __restrict__ in)
{
    int i = blockIdx.x * 256 + threadIdx.x;
    float4 v = ((const float4*)in)[i];
    ((__half2*)g_x)[2 * i]     = __floats2half2_rn(v.x, v.y);
    ((__half2*)g_x)[2 * i + 1] = __floats2half2_rn(v.z, v.w);
}

__global__ void __launch_bounds__(256)
conv_wT_kernel(const float* __restrict__ Wq, const float* __restrict__ Wk,
               const float* __restrict__ Wv, const float* __restrict__ Wo)
{
    const float* W = (blockIdx.z == 0) ? Wq : (blockIdx.z == 1) ? Wk
                    : (blockIdx.z == 2) ? Wv : Wo;
    __half* T = g_wT + (size_t)blockIdx.z * DD;

    __shared__ float tile[32][33];
    const int tx = threadIdx.x & 31, ty = threadIdx.x >> 5;
    const int n0 = blockIdx.x * 32, k0 = blockIdx.y * 32;
#pragma unroll
    for (int i = 0; i < 4; i++)
        tile[ty + 8 * i][tx] = W[(size_t)(k0 + ty + 8 * i) * D_ + n0 + tx];
    __syncthreads();
#pragma unroll
    for (int i = 0; i < 4; i++)
        T[(size_t)(n0 + ty + 8 * i) * D_ + k0 + tx] = __float2half(tile[tx][ty + 8 * i]);
}

// ---------------------------------------------------------------------------
// HMMA fp16 GEMM: C = A @ B^T (B stored [n][k]).  (R13 structure — WIN)
// CTA 128x128, 8 warps (2m x 4n), K-chunk 64, 3-stage cp.async ring.
// mode: 0 -> fp32 C + bias; 1 -> fp16 C.
// ---------------------------------------------------------------------------
#define KCH   64
#define NCH   (D_ / KCH)        // 16
#define LDKB  144               // 64 fp16 (128B) + 16B pad
#define T_A    0
#define T_B    18432
#define STAGE  36864
#define GSMEM  (3 * STAGE)      // 110592

__device__ __forceinline__ void hmma_gemm_body(
    const __half* __restrict__ A, const __half* __restrict__ B,
    float* __restrict__ C, const float* __restrict__ bias,
    __half* __restrict__ Ch, int mode)
{
    extern __shared__ char sm[];
    const uint32_t sb = smem_u32(sm);
    const int tid  = threadIdx.x;
    const int lane = tid & 31;
    const int wid  = tid >> 5;
    const int wm   = (wid & 1) * 64;
    const int wn   = (wid >> 1) * 32;
    const int m0   = blockIdx.y * 128;
    const int n0   = blockIdx.x * 128;

    const uint32_t aoff = (uint32_t)((wm + (lane & 15)) * LDKB + (lane >> 4) * 16);
    const uint32_t boff = (uint32_t)((wn + (lane & 7) + ((lane >> 4) & 1) * 8) * LDKB
                                     + ((lane >> 3) & 1) * 16);

    float acc[4][4][4];
#pragma unroll
    for (int i = 0; i < 4; i++)
#pragma unroll
        for (int j = 0; j < 4; j++)
#pragma unroll
            for (int q = 0; q < 4; q++) acc[i][j][q] = 0.f;

    auto issue = [&](int c, int s) {
        const int k0 = c * KCH;
        const uint32_t st = sb + s * STAGE;
#pragma unroll
        for (int t = 0; t < 4; t++) {
            int idx = tid + t * 256;
            int row = idx >> 3, q = idx & 7;
            uint32_t so = (uint32_t)(row * LDKB + q * 16);
            cp16(st + T_A + so, A + (size_t)(m0 + row) * D_ + k0 + q * 8);
            cp16(st + T_B + so, B + (size_t)(n0 + row) * D_ + k0 + q * 8);
        }
        CP_COMMIT();
    };

    issue(0, 0);
    issue(1, 1);
    for (int c = 0; c < NCH; ++c) {
        if (c + 1 < NCH) CP_WAIT1(); else CP_WAIT0();
        __syncthreads();
        if (c + 2 < NCH) issue(c + 2, (c + 2) % 3);

        const uint32_t st = sb + (c % 3) * STAGE;
        const uint32_t a_b = st + T_A + aoff;
        const uint32_t b_b = st + T_B + boff;

#pragma unroll
        for (int ks = 0; ks < 4; ks++) {
            const uint32_t ko = ks * 32;
            uint32_t ah[4][4], bf[2][4];
#pragma unroll
            for (int i = 0; i < 4; i++)
                ldm4(ah[i], a_b + ko + i * (16 * LDKB));
#pragma unroll
            for (int jp = 0; jp < 2; jp++)
                ldm4(bf[jp], b_b + ko + jp * (16 * LDKB));
#pragma unroll
            for (int i = 0; i < 4; i++)
#pragma unroll
                for (int jp = 0; jp < 2; jp++) {
                    hmma(acc[i][2 * jp],     ah[i], bf[jp]);
                    hmma(acc[i][2 * jp + 1], ah[i], bf[jp] + 2);
                }
        }
    }

    const int gid = lane >> 2, tig = lane & 3;
#pragma unroll
    for (int i = 0; i < 4; i++) {
        const int row = m0 + wm + i * 16 + gid;
#pragma unroll
        for (int j = 0; j < 4; j++) {
            const int col = n0 + wn + j * 8 + tig * 2;
            size_t o0 = (size_t)row * D_ + col;
            size_t o1 = (size_t)(row + 8) * D_ + col;
            if (mode == 1) {
                *(__half2*)(Ch + o0) = __floats2half2_rn(acc[i][j][0], acc[i][j][1]);
                *(__half2*)(Ch + o1) = __floats2half2_rn(acc[i][j][2], acc[i][j][3]);
            } else {
                float b0 = bias[col], b1 = bias[col + 1];
                *(float2*)(C + o0) = make_float2(acc[i][j][0] + b0, acc[i][j][1] + b1);
                *(float2*)(C + o1) = make_float2(acc[i][j][2] + b0, acc[i][j][3] + b1);
            }
        }
    }
}

__global__ void __launch_bounds__(256, 2)
hmma_qkv_kernel()
{
    const int z = blockIdx.z;
    __half* Ch = (z == 0) ? g_q : (z == 1) ? g_k : g_v;
    hmma_gemm_body(g_x, g_wT + (size_t)z * DD, nullptr, nullptr, Ch, 1);
}

__global__ void __launch_bounds__(256, 2)
hmma_out_kernel(const float* __restrict__ bo, float* __restrict__ out)
{
    hmma_gemm_body(g_a, g_wT + 3ull * DD, out, bo, nullptr, 0);
}

// ---------------------------------------------------------------------------
// HMMA flash attention — EXACT R12 structure (measured best: 85.2us).
// Single fp16 Q/K/V/P. CTA = (qb,h,b); 8 warps x 16 rows; 2-stage KV ring.
// ---------------------------------------------------------------------------
#define FQ    0
#define FST   18432          // stages base (Q tile = 128*144)
#define FSTG  18432          // per-stage: K at 0 (9216), V at 9216
#define FSMEM (FST + 2 * FSTG)   // 55296
#define QSC   0.1803368801f  // 0.125 * log2(e)

template<bool MASKED>
__device__ __forceinline__ void ftile(
    uint32_t st, int kv0, int row0, int row1, int lane,
    const uint32_t (&qh)[4][4],
    float& m0, float& m1, float& l0, float& l1, float (&O)[8][4])
{
    const int tig = lane & 3;
    float s[8][4];
#pragma unroll
    for (int j = 0; j < 8; j++)
#pragma unroll
        for (int c = 0; c < 4; c++) s[j][c] = 0.f;

    // ---- S = Q @ K^T  (K x4: j and j+1 per load)
    const uint32_t kb0 = st + (uint32_t)(((lane & 7) + ((lane >> 4) & 1) * 8) * 144
                                         + ((lane >> 3) & 1) * 16);
#pragma unroll
    for (int kk = 0; kk < 4; kk++) {
        const uint32_t kb = kb0 + kk * 32;
#pragma unroll
        for (int j = 0; j < 8; j += 2) {
            uint32_t kf[4];
            ldm4(kf, kb + j * (8 * 144));
            hmma(s[j],     qh[kk], kf);
            hmma(s[j + 1], qh[kk], kf + 2);
        }
    }

    // ---- scale + mask + row max
    float mx0 = -1e30f, mx1 = -1e30f;
#pragma unroll
    for (int j = 0; j < 8; j++) {
#pragma unroll
        for (int c = 0; c < 4; c++) {
            float v = s[j][c] * QSC;
            if (MASKED) {
                int col = kv0 + j * 8 + tig * 2 + (c & 1);
                int row = (c < 2) ? row0 : row1;
                if (col > row) v = -1e30f;
            }
            s[j][c] = v;
            if (c < 2) mx0 = fmaxf(mx0, v); else mx1 = fmaxf(mx1, v);
        }
    }
    mx0 = qmax(mx0); mx1 = qmax(mx1);
    const float m0n = fmaxf(m0, mx0), m1n = fmaxf(m1, mx1);
    const float a0 = ex2(m0 - m0n), a1 = ex2(m1 - m1n);
    m0 = m0n; m1 = m1n;

    float ts0 = 0.f, ts1 = 0.f;
    uint32_t pH[2][8];
#pragma unroll
    for (int j = 0; j < 8; j++) {
        float p00 = ex2(s[j][0] - m0n), p01 = ex2(s[j][1] - m0n);
        float p10 = ex2(s[j][2] - m1n), p11 = ex2(s[j][3] - m1n);
        if (MASKED) {   // guard fully-masked lanes
            if (s[j][0] < -1e29f) p00 = 0.f;
            if (s[j][1] < -1e29f) p01 = 0.f;
            if (s[j][2] < -1e29f) p10 = 0.f;
            if (s[j][3] < -1e29f) p11 = 0.f;
        }
        ts0 += p00 + p01; ts1 += p10 + p11;
        pH[0][j] = packh(p00, p01);
        pH[1][j] = packh(p10, p11);
    }
    ts0 = qsum(ts0); ts1 = qsum(ts1);
    l0 = l0 * a0 + ts0;
    l1 = l1 * a1 + ts1;
#pragma unroll
    for (int j = 0; j < 8; j++) {
        O[j][0] *= a0; O[j][1] *= a0; O[j][2] *= a1; O[j][3] *= a1;
    }

    // ---- O += P @ V  (V x4 trans: j and j+1 per load)
    const uint32_t vb0 = st + 9216
        + (uint32_t)(((lane & 7) + ((lane >> 3) & 1) * 8) * 144
                     + ((lane >> 4) & 1) * 16);
#pragma unroll
    for (int kk = 0; kk < 4; kk++) {
        uint32_t ah[4] = { pH[0][2 * kk], pH[1][2 * kk],
                           pH[0][2 * kk + 1], pH[1][2 * kk + 1] };
        const uint32_t vb = vb0 + kk * (16 * 144);
#pragma unroll
        for (int j = 0; j < 8; j += 2) {
            uint32_t vf[4];
            ldm4t(vf, vb + j * 16);
            hmma(O[j],     ah, vf);
            hmma(O[j + 1], ah, vf + 2);
        }
    }
}

__global__ void __launch_bounds__(256, 2)
flash_hmma_kernel()
{
    extern __shared__ char fsm[];
    const uint32_t sb = smem_u32(fsm);
    const int tid = threadIdx.x, lane = tid & 31, wid = tid >> 5;
    const int qb = gridDim.x - 1 - blockIdx.x;   // big tiles first
    const int h = blockIdx.y, b = blockIdx.z;
    const int ntiles = qb * 2 + 2;

    auto issueT = [&](int t, int s) {
        const uint32_t st = sb + FST + s * FSTG;
        const int kv0 = t * 64;
#pragma unroll
        for (int i = 0; i < 2; i++) {
            int c = tid + i * 256;
            int row = c >> 3, q = c & 7;
            size_t g = (size_t)(b * S_ + kv0 + row) * D_ + h * HD_ + q * 8;
            uint32_t so = (uint32_t)(row * 144 + q * 16);
            cp16(st + so,        g_k + g);
            cp16(st + 9216 + so, g_v + g);
        }
        CP_COMMIT();
    };

    // Q + tile0 (group 0), tile1 (group 1)
    {
#pragma unroll
        for (int i = 0; i < 4; i++) {
            int c = tid + i * 256;
            int row = c >> 3, q = c & 7;
            size_t g = (size_t)(b * S_ + qb * 128 + row) * D_ + h * HD_ + q * 8;
            cp16(sb + FQ + (uint32_t)(row * 144 + q * 16), g_q + g);
        }
        const uint32_t st = sb + FST;
#pragma unroll
        for (int i = 0; i < 2; i++) {
            int c = tid + i * 256;
            int row = c >> 3, q = c & 7;
            size_t g = (size_t)(b * S_ + row) * D_ + h * HD_ + q * 8;
            uint32_t so = (uint32_t)(row * 144 + q * 16);
            cp16(st + so,        g_k + g);
            cp16(st + 9216 + so, g_v + g);
        }
        CP_COMMIT();
        issueT(1, 1);
    }

    const int gid = lane >> 2;
    const int q0w = qb * 128 + wid * 16;
    const int row0 = q0w + gid, row1 = row0 + 8;
    float m0 = -1e30f, m1 = -1e30f, l0 = 0.f, l1 = 0.f;
    float O[8][4];
#pragma unroll
    for (int j = 0; j < 8; j++)
#pragma unroll
        for (int c = 0; c < 4; c++) O[j][c] = 0.f;
    uint32_t qh[4][4];
    bool qloaded = false;

    for (int t = 0; t < ntiles; t++) {
        if (t + 1 < ntiles) CP_WAIT1(); else CP_WAIT0();
        __syncthreads();
        if (!qloaded) {
            const uint32_t qa = (uint32_t)((wid * 16 + (lane & 15)) * 144
                                           + (lane >> 4) * 16);
#pragma unroll
            for (int kk = 0; kk < 4; kk++)
                ldm4(qh[kk], sb + FQ + qa + kk * 32);
            qloaded = true;
        }
        const uint32_t st = sb + FST + (t & 1) * FSTG;
        const int kv0 = t * 64;
        if (q0w + 15 >= kv0) {
            if (kv0 + 63 > q0w)
                ftile<true >(st, kv0, row0, row1, lane, qh, m0, m1, l0, l1, O);
            else
                ftile<false>(st, kv0, row0, row1, lane, qh, m0, m1, l0, l1, O);
        }
        __syncthreads();
        if (t + 2 < ntiles) issueT(t + 2, t & 1);
    }

    // epilogue: normalize, write fp16 mis-reshaped layout
    const float inv0 = 1.f / l0, inv1 = 1.f / l1;
    const int tig = lane & 3;
#pragma unroll
    for (int j = 0; j < 8; j++) {
        const int d = j * 8 + tig * 2;
        size_t o0 = (size_t)(b * S_ + h * 128 + (row0 >> 4)) * D_ + (row0 & 15) * 64 + d;
        size_t o1 = (size_t)(b * S_ + h * 128 + (row1 >> 4)) * D_ + (row1 & 15) * 64 + d;
        *(__half2*)(g_a + o0) = __floats2half2_rn(O[j][0] * inv0, O[j][1] * inv0);
        *(__half2*)(g_a + o1) = __floats2half2_rn(O[j][2] * inv1, O[j][3] * inv1);
    }
}

// ---------------------------------------------------------------------------
// Launch
// ---------------------------------------------------------------------------
extern "C" void kernel_launch(void* const* d_in, const int* in_sizes, int n_in,
                              void* d_out, int out_size)
{
    const float* x  = (const float*)d_in[0];
    const float* Wq = (const float*)d_in[1];
    const float* Wk = (const float*)d_in[2];
    const float* Wv = (const float*)d_in[3];
    const float* Wo = (const float*)d_in[4];
    const float* bo = (const float*)d_in[5];
    float* out = (float*)d_out;

    cudaFuncSetAttribute(hmma_qkv_kernel,
                         cudaFuncAttributeMaxDynamicSharedMemorySize, GSMEM);
    cudaFuncSetAttribute(hmma_out_kernel,
                         cudaFuncAttributeMaxDynamicSharedMemorySize, GSMEM);
    cudaFuncSetAttribute(flash_hmma_kernel,
                         cudaFuncAttributeMaxDynamicSharedMemorySize, FSMEM);

    const int n4 = MTOT * D_ / 4;

    conv_x_kernel<<<n4 / 256, 256>>>(x);
    conv_wT_kernel<<<dim3(32, 32, 4), 256>>>(Wq, Wk, Wv, Wo);

    hmma_qkv_kernel<<<dim3(D_ / 128, MTOT / 128, 3), 256, GSMEM>>>();

    flash_hmma_kernel<<<dim3(S_ / 128, H_, B_), 256, FSMEM>>>();

    hmma_out_kernel<<<dim3(D_ / 128, MTOT / 128, 1), 256, GSMEM>>>(bo, out);
}

// round 17
// speedup vs baseline: 1.0196x; 1.0021x over previous
#include <cuda_runtime.h>
#include <cuda_fp16.h>
#include <cstdint>

#define B_   2
#define S_   2048
#define D_   1024
#define H_   16
#define HD_  64
#define MTOT (B_ * S_)   // 4096
#define DD   (D_ * D_)

// ---------------------------------------------------------------------------
// Device scratch (static — no cudaMalloc allowed). Single fp16 everywhere.
// ---------------------------------------------------------------------------
__device__ __half g_x[MTOT * D_];
__device__ __half g_q[MTOT * D_];
__device__ __half g_k[MTOT * D_];
__device__ __half g_v[MTOT * D_];
__device__ __half g_a[MTOT * D_];        // attn out (mis-reshaped layout)
__device__ __half g_wT[4 * DD];          // W^T [n][k], q/k/v/o

// ---------------------------------------------------------------------------
// PTX helpers (sm_80+ only: cp.async, ldmatrix, mma.sync)
// ---------------------------------------------------------------------------
__device__ __forceinline__ uint32_t smem_u32(const void* p) {
    uint32_t a;
    asm("{ .reg .u64 t; cvta.to.shared.u64 t, %1; cvt.u32.u64 %0, t; }"
        : "=r"(a) : "l"(p));
    return a;
}
__device__ __forceinline__ void cp16(uint32_t d, const void* s) {
    asm volatile("cp.async.cg.shared.global [%0], [%1], 16;" :: "r"(d), "l"(s));
}
#define CP_COMMIT() asm volatile("cp.async.commit_group;")
#define CP_WAIT1()  asm volatile("cp.async.wait_group 1;")
#define CP_WAIT0()  asm volatile("cp.async.wait_group 0;")

__device__ __forceinline__ void ldm4(uint32_t* r, uint32_t a) {
    asm volatile("ldmatrix.sync.aligned.m8n8.x4.shared.b16 {%0,%1,%2,%3}, [%4];"
                 : "=r"(r[0]), "=r"(r[1]), "=r"(r[2]), "=r"(r[3]) : "r"(a));
}
__device__ __forceinline__ void ldm4t(uint32_t* r, uint32_t a) {
    asm volatile("ldmatrix.sync.aligned.m8n8.x4.trans.shared.b16 {%0,%1,%2,%3}, [%4];"
                 : "=r"(r[0]), "=r"(r[1]), "=r"(r[2]), "=r"(r[3]) : "r"(a));
}
__device__ __forceinline__ void hmma(float* c, const uint32_t* a, const uint32_t* b) {
    asm volatile(
        "mma.sync.aligned.m16n8k16.row.col.f32.f16.f16.f32 "
        "{%0,%1,%2,%3}, {%4,%5,%6,%7}, {%8,%9}, {%0,%1,%2,%3};"
        : "+f"(c[0]), "+f"(c[1]), "+f"(c[2]), "+f"(c[3])
        : "r"(a[0]), "r"(a[1]), "r"(a[2]), "r"(a[3]), "r"(b[0]), "r"(b[1]));
}
__device__ __forceinline__ float ex2(float x) {
    float r; asm("ex2.approx.ftz.f32 %0, %1;" : "=f"(r) : "f"(x)); return r;
}
__device__ __forceinline__ float qmax(float v) {
    v = fmaxf(v, __shfl_xor_sync(0xFFFFFFFFu, v, 1));
    v = fmaxf(v, __shfl_xor_sync(0xFFFFFFFFu, v, 2));
    return v;
}
__device__ __forceinline__ float qsum(float v) {
    v += __shfl_xor_sync(0xFFFFFFFFu, v, 1);
    v += __shfl_xor_sync(0xFFFFFFFFu, v, 2);
    return v;
}
__device__ __forceinline__ uint32_t packh(float a, float b) {
    __half2 t = __floats2half2_rn(a, b);
    return *(uint32_t*)&t;
}

// ---------------------------------------------------------------------------
// Merged conversion kernel: grid (32, 32, 5).
//   z in [0,3]: transpose+convert W_z 32x32 tile -> g_wT
//   z == 4   : convert x -> fp16 (each block does 4 float4 chunks)
// ---------------------------------------------------------------------------
__global__ void __launch_bounds__(256)
conv_all_kernel(const float* __restrict__ x,
                const float* __restrict__ Wq, const float* __restrict__ Wk,
                const float* __restrict__ Wv, const float* __restrict__ Wo)
{
    const int z = blockIdx.z;
    if (z == 4) {
        const int flat = blockIdx.y * 32 + blockIdx.x;   // 0..1023
#pragma unroll
        for (int t = 0; t < 4; t++) {
            int i = flat * 1024 + t * 256 + threadIdx.x;
            float4 v = ((const float4*)x)[i];
            ((__half2*)g_x)[2 * i]     = __floats2half2_rn(v.x, v.y);
            ((__half2*)g_x)[2 * i + 1] = __floats2half2_rn(v.z, v.w);
        }
        return;
    }

    const float* W = (z == 0) ? Wq : (z == 1) ? Wk : (z == 2) ? Wv : Wo;
    __half* T = g_wT + (size_t)z * DD;

    __shared__ float tile[32][33];
    const int tx = threadIdx.x & 31, ty = threadIdx.x >> 5;
    const int n0 = blockIdx.x * 32, k0 = blockIdx.y * 32;
#pragma unroll
    for (int i = 0; i < 4; i++)
        tile[ty + 8 * i][tx] = W[(size_t)(k0 + ty + 8 * i) * D_ + n0 + tx];
    __syncthreads();
#pragma unroll
    for (int i = 0; i < 4; i++)
        T[(size_t)(n0 + ty + 8 * i) * D_ + k0 + tx] = __float2half(tile[tx][ty + 8 * i]);
}

// ---------------------------------------------------------------------------
// HMMA fp16 GEMM tile body (R13 ring structure — WIN).
// CTA 128x128 tile, 8 warps (2m x 4n), K-chunk 64, 3-stage cp.async ring.
// mode: 0 -> fp32 C + bias; 1 -> fp16 C.
// ---------------------------------------------------------------------------
#define KCH   64
#define NCH   (D_ / KCH)        // 16
#define LDKB  144               // 64 fp16 (128B) + 16B pad
#define T_A    0
#define T_B    18432
#define STAGE  36864
#define GSMEM  (3 * STAGE)      // 110592

__device__ __forceinline__ void hmma_gemm_tile(
    const __half* __restrict__ A, const __half* __restrict__ B,
    float* __restrict__ C, const float* __restrict__ bias,
    __half* __restrict__ Ch, int mode, int m0, int n0)
{
    extern __shared__ char sm[];
    const uint32_t sb = smem_u32(sm);
    const int tid  = threadIdx.x;
    const int lane = tid & 31;
    const int wid  = tid >> 5;
    const int wm   = (wid & 1) * 64;
    const int wn   = (wid >> 1) * 32;

    const uint32_t aoff = (uint32_t)((wm + (lane & 15)) * LDKB + (lane >> 4) * 16);
    const uint32_t boff = (uint32_t)((wn + (lane & 7) + ((lane >> 4) & 1) * 8) * LDKB
                                     + ((lane >> 3) & 1) * 16);

    float acc[4][4][4];
#pragma unroll
    for (int i = 0; i < 4; i++)
#pragma unroll
        for (int j = 0; j < 4; j++)
#pragma unroll
            for (int q = 0; q < 4; q++) acc[i][j][q] = 0.f;

    auto issue = [&](int c, int s) {
        const int k0 = c * KCH;
        const uint32_t st = sb + s * STAGE;
#pragma unroll
        for (int t = 0; t < 4; t++) {
            int idx = tid + t * 256;
            int row = idx >> 3, q = idx & 7;
            uint32_t so = (uint32_t)(row * LDKB + q * 16);
            cp16(st + T_A + so, A + (size_t)(m0 + row) * D_ + k0 + q * 8);
            cp16(st + T_B + so, B + (size_t)(n0 + row) * D_ + k0 + q * 8);
        }
        CP_COMMIT();
    };

    issue(0, 0);
    issue(1, 1);
    for (int c = 0; c < NCH; ++c) {
        if (c + 1 < NCH) CP_WAIT1(); else CP_WAIT0();
        __syncthreads();
        if (c + 2 < NCH) issue(c + 2, (c + 2) % 3);

        const uint32_t st = sb + (c % 3) * STAGE;
        const uint32_t a_b = st + T_A + aoff;
        const uint32_t b_b = st + T_B + boff;

#pragma unroll
        for (int ks = 0; ks < 4; ks++) {
            const uint32_t ko = ks * 32;
            uint32_t ah[4][4], bf[2][4];
#pragma unroll
            for (int i = 0; i < 4; i++)
                ldm4(ah[i], a_b + ko + i * (16 * LDKB));
#pragma unroll
            for (int jp = 0; jp < 2; jp++)
                ldm4(bf[jp], b_b + ko + jp * (16 * LDKB));
#pragma unroll
            for (int i = 0; i < 4; i++)
#pragma unroll
                for (int jp = 0; jp < 2; jp++) {
                    hmma(acc[i][2 * jp],     ah[i], bf[jp]);
                    hmma(acc[i][2 * jp + 1], ah[i], bf[jp] + 2);
                }
        }
    }

    const int gid = lane >> 2, tig = lane & 3;
#pragma unroll
    for (int i = 0; i < 4; i++) {
        const int row = m0 + wm + i * 16 + gid;
#pragma unroll
        for (int j = 0; j < 4; j++) {
            const int col = n0 + wn + j * 8 + tig * 2;
            size_t o0 = (size_t)row * D_ + col;
            size_t o1 = (size_t)(row + 8) * D_ + col;
            if (mode == 1) {
                *(__half2*)(Ch + o0) = __floats2half2_rn(acc[i][j][0], acc[i][j][1]);
                *(__half2*)(Ch + o1) = __floats2half2_rn(acc[i][j][2], acc[i][j][3]);
            } else {
                float b0 = bias[col], b1 = bias[col + 1];
                *(float2*)(C + o0) = make_float2(acc[i][j][0] + b0, acc[i][j][1] + b1);
                *(float2*)(C + o1) = make_float2(acc[i][j][2] + b0, acc[i][j][3] + b1);
            }
        }
    }
}

// Persistent qkv: 296 CTAs loop over 768 tiles (3 z x 32 m x 8 n).
#define QKV_TILES (3 * 32 * 8)
#define QKV_CTAS  296

__global__ void __launch_bounds__(256, 2)
hmma_qkv_kernel()
{
    for (int idx = blockIdx.x; idx < QKV_TILES; idx += QKV_CTAS) {
        const int z = idx >> 8;            // 0..2
        const int r = idx & 255;
        const int m0 = (r >> 3) * 128;
        const int n0 = (r & 7) * 128;
        __half* Ch = (z == 0) ? g_q : (z == 1) ? g_k : g_v;
        if (idx != blockIdx.x) __syncthreads();   // prior tile smem reads done
        hmma_gemm_tile(g_x, g_wT + (size_t)z * DD, nullptr, nullptr, Ch, 1, m0, n0);
    }
}

__global__ void __launch_bounds__(256, 2)
hmma_out_kernel(const float* __restrict__ bo, float* __restrict__ out)
{
    hmma_gemm_tile(g_a, g_wT + 3ull * DD, out, bo, nullptr, 0,
                   blockIdx.y * 128, blockIdx.x * 128);
}

// ---------------------------------------------------------------------------
// HMMA flash attention — EXACT R12 structure (measured best).
// Single fp16 Q/K/V/P. CTA = (qb,h,b); 8 warps x 16 rows; 2-stage KV ring.
// ---------------------------------------------------------------------------
#define FQ    0
#define FST   18432          // stages base (Q tile = 128*144)
#define FSTG  18432          // per-stage: K at 0 (9216), V at 9216
#define FSMEM (FST + 2 * FSTG)   // 55296
#define QSC   0.1803368801f  // 0.125 * log2(e)

template<bool MASKED>
__device__ __forceinline__ void ftile(
    uint32_t st, int kv0, int row0, int row1, int lane,
    const uint32_t (&qh)[4][4],
    float& m0, float& m1, float& l0, float& l1, float (&O)[8][4])
{
    const int tig = lane & 3;
    float s[8][4];
#pragma unroll
    for (int j = 0; j < 8; j++)
#pragma unroll
        for (int c = 0; c < 4; c++) s[j][c] = 0.f;

    // ---- S = Q @ K^T  (K x4: j and j+1 per load)
    const uint32_t kb0 = st + (uint32_t)(((lane & 7) + ((lane >> 4) & 1) * 8) * 144
                                         + ((lane >> 3) & 1) * 16);
#pragma unroll
    for (int kk = 0; kk < 4; kk++) {
        const uint32_t kb = kb0 + kk * 32;
#pragma unroll
        for (int j = 0; j < 8; j += 2) {
            uint32_t kf[4];
            ldm4(kf, kb + j * (8 * 144));
            hmma(s[j],     qh[kk], kf);
            hmma(s[j + 1], qh[kk], kf + 2);
        }
    }

    // ---- scale + mask + row max
    float mx0 = -1e30f, mx1 = -1e30f;
#pragma unroll
    for (int j = 0; j < 8; j++) {
#pragma unroll
        for (int c = 0; c < 4; c++) {
            float v = s[j][c] * QSC;
            if (MASKED) {
                int col = kv0 + j * 8 + tig * 2 + (c & 1);
                int row = (c < 2) ? row0 : row1;
                if (col > row) v = -1e30f;
            }
            s[j][c] = v;
            if (c < 2) mx0 = fmaxf(mx0, v); else mx1 = fmaxf(mx1, v);
        }
    }
    mx0 = qmax(mx0); mx1 = qmax(mx1);
    const float m0n = fmaxf(m0, mx0), m1n = fmaxf(m1, mx1);
    const float a0 = ex2(m0 - m0n), a1 = ex2(m1 - m1n);
    m0 = m0n; m1 = m1n;

    float ts0 = 0.f, ts1 = 0.f;
    uint32_t pH[2][8];
#pragma unroll
    for (int j = 0; j < 8; j++) {
        float p00 = ex2(s[j][0] - m0n), p01 = ex2(s[j][1] - m0n);
        float p10 = ex2(s[j][2] - m1n), p11 = ex2(s[j][3] - m1n);
        if (MASKED) {   // guard fully-masked lanes
            if (s[j][0] < -1e29f) p00 = 0.f;
            if (s[j][1] < -1e29f) p01 = 0.f;
            if (s[j][2] < -1e29f) p10 = 0.f;
            if (s[j][3] < -1e29f) p11 = 0.f;
        }
        ts0 += p00 + p01; ts1 += p10 + p11;
        pH[0][j] = packh(p00, p01);
        pH[1][j] = packh(p10, p11);
    }
    ts0 = qsum(ts0); ts1 = qsum(ts1);
    l0 = l0 * a0 + ts0;
    l1 = l1 * a1 + ts1;
#pragma unroll
    for (int j = 0; j < 8; j++) {
        O[j][0] *= a0; O[j][1] *= a0; O[j][2] *= a1; O[j][3] *= a1;
    }

    // ---- O += P @ V  (V x4 trans: j and j+1 per load)
    const uint32_t vb0 = st + 9216
        + (uint32_t)(((lane & 7) + ((lane >> 3) & 1) * 8) * 144
                     + ((lane >> 4) & 1) * 16);
#pragma unroll
    for (int kk = 0; kk < 4; kk++) {
        uint32_t ah[4] = { pH[0][2 * kk], pH[1][2 * kk],
                           pH[0][2 * kk + 1], pH[1][2 * kk + 1] };
        const uint32_t vb = vb0 + kk * (16 * 144);
#pragma unroll
        for (int j = 0; j < 8; j += 2) {
            uint32_t vf[4];
            ldm4t(vf, vb + j * 16);
            hmma(O[j],     ah, vf);
            hmma(O[j + 1], ah, vf + 2);
        }
    }
}

__global__ void __launch_bounds__(256, 2)
flash_hmma_kernel()
{
    extern __shared__ char fsm[];
    const uint32_t sb = smem_u32(fsm);
    const int tid = threadIdx.x, lane = tid & 31, wid = tid >> 5;
    const int qb = gridDim.x - 1 - blockIdx.x;   // big tiles first
    const int h = blockIdx.y, b = blockIdx.z;
    const int ntiles = qb * 2 + 2;

    auto issueT = [&](int t, int s) {
        const uint32_t st = sb + FST + s * FSTG;
        const int kv0 = t * 64;
#pragma unroll
        for (int i = 0; i < 2; i++) {
            int c = tid + i * 256;
            int row = c >> 3, q = c & 7;
            size_t g = (size_t)(b * S_ + kv0 + row) * D_ + h * HD_ + q * 8;
            uint32_t so = (uint32_t)(row * 144 + q * 16);
            cp16(st + so,        g_k + g);
            cp16(st + 9216 + so, g_v + g);
        }
        CP_COMMIT();
    };

    // Q + tile0 (group 0), tile1 (group 1)
    {
#pragma unroll
        for (int i = 0; i < 4; i++) {
            int c = tid + i * 256;
            int row = c >> 3, q = c & 7;
            size_t g = (size_t)(b * S_ + qb * 128 + row) * D_ + h * HD_ + q * 8;
            cp16(sb + FQ + (uint32_t)(row * 144 + q * 16), g_q + g);
        }
        const uint32_t st = sb + FST;
#pragma unroll
        for (int i = 0; i < 2; i++) {
            int c = tid + i * 256;
            int row = c >> 3, q = c & 7;
            size_t g = (size_t)(b * S_ + row) * D_ + h * HD_ + q * 8;
            uint32_t so = (uint32_t)(row * 144 + q * 16);
            cp16(st + so,        g_k + g);
            cp16(st + 9216 + so, g_v + g);
        }
        CP_COMMIT();
        issueT(1, 1);
    }

    const int gid = lane >> 2;
    const int q0w = qb * 128 + wid * 16;
    const int row0 = q0w + gid, row1 = row0 + 8;
    float m0 = -1e30f, m1 = -1e30f, l0 = 0.f, l1 = 0.f;
    float O[8][4];
#pragma unroll
    for (int j = 0; j < 8; j++)
#pragma unroll
        for (int c = 0; c < 4; c++) O[j][c] = 0.f;
    uint32_t qh[4][4];
    bool qloaded = false;

    for (int t = 0; t < ntiles; t++) {
        if (t + 1 < ntiles) CP_WAIT1(); else CP_WAIT0();
        __syncthreads();
        if (!qloaded) {
            const uint32_t qa = (uint32_t)((wid * 16 + (lane & 15)) * 144
                                           + (lane >> 4) * 16);
#pragma unroll
            for (int kk = 0; kk < 4; kk++)
                ldm4(qh[kk], sb + FQ + qa + kk * 32);
            qloaded = true;
        }
        const uint32_t st = sb + FST + (t & 1) * FSTG;
        const int kv0 = t * 64;
        if (q0w + 15 >= kv0) {
            if (kv0 + 63 > q0w)
                ftile<true >(st, kv0, row0, row1, lane, qh, m0, m1, l0, l1, O);
            else
                ftile<false>(st, kv0, row0, row1, lane, qh, m0, m1, l0, l1, O);
        }
        __syncthreads();
        if (t + 2 < ntiles) issueT(t + 2, t & 1);
    }

    // epilogue: normalize, write fp16 mis-reshaped layout
    const float inv0 = 1.f / l0, inv1 = 1.f / l1;
    const int tig = lane & 3;
#pragma unroll
    for (int j = 0; j < 8; j++) {
        const int d = j * 8 + tig * 2;
        size_t o0 = (size_t)(b * S_ + h * 128 + (row0 >> 4)) * D_ + (row0 & 15) * 64 + d;
        size_t o1 = (size_t)(b * S_ + h * 128 + (row1 >> 4)) * D_ + (row1 & 15) * 64 + d;
        *(__half2*)(g_a + o0) = __floats2half2_rn(O[j][0] * inv0, O[j][1] * inv0);
        *(__half2*)(g_a + o1) = __floats2half2_rn(O[j][2] * inv1, O[j][3] * inv1);
    }
}

// ---------------------------------------------------------------------------
// Launch
// ---------------------------------------------------------------------------
extern "C" void kernel_launch(void* const* d_in, const int* in_sizes, int n_in,
                              void* d_out, int out_size)
{
    const float* x  = (const float*)d_in[0];
    const float* Wq = (const float*)d_in[1];
    const float* Wk = (const float*)d_in[2];
    const float* Wv = (const float*)d_in[3];
    const float* Wo = (const float*)d_in[4];
    const float* bo = (const float*)d_in[5];
    float* out = (float*)d_out;

    cudaFuncSetAttribute(hmma_qkv_kernel,
                         cudaFuncAttributeMaxDynamicSharedMemorySize, GSMEM);
    cudaFuncSetAttribute(hmma_out_kernel,
                         cudaFuncAttributeMaxDynamicSharedMemorySize, GSMEM);
    cudaFuncSetAttribute(flash_hmma_kernel,
                         cudaFuncAttributeMaxDynamicSharedMemorySize, FSMEM);

    conv_all_kernel<<<dim3(32, 32, 5), 256>>>(x, Wq, Wk, Wv, Wo);

    hmma_qkv_kernel<<<QKV_CTAS, 256, GSMEM>>>();

    flash_hmma_kernel<<<dim3(S_ / 128, H_, B_), 256, FSMEM>>>();

    hmma_out_kernel<<<dim3(D_ / 128, MTOT / 128, 1), 256, GSMEM>>>(bo, out);
}